// round 1
// baseline (speedup 1.0000x reference)
#include <cuda_runtime.h>
#include <math.h>
#include <limits.h>

#define NMESH  256
#define MSTEPS 4096
#define SLEN   (MSTEPS + 1)   // scan steps 0..M (step 0 = pseudo init sweep-up at hc=1.0)
#define LOGS   13
#define TRI    (NMESH * (NMESH + 1) / 2)

// ---------------- device scratch (no allocations allowed) ----------------
__device__ float  g_P[TRI];               // per-row inclusive prefix of softplus density
__device__ float  g_rowsum[NMESH];
__device__ double g_A[NMESH + 1];         // A[i] = sum_{k<i} rowsum_k ; A[NMESH] = S
__device__ double g_colpre[NMESH * NMESH];// colpre[j*N+i] = sum_{k=j..i} P_k(j)
__device__ int    g_iu[SLEN];             // up-step: #rows with alpha < hc, else 0
__device__ int    g_d[SLEN];              // down-step: max j with beta_j <= hc, else INT_MAX
__device__ int    g_lastup[SLEN];         // last up-step index <= s
__device__ int    g_link[SLEN];           // previous up-step with strictly greater iu
__device__ int    g_STd[LOGS * SLEN];     // sparse table: range-min over g_d
__device__ int    g_STu[LOGS * SLEN];     // sparse table: range-max over g_iu

__device__ __forceinline__ float softplusf(float x) {
    return fmaxf(x, 0.f) + log1pf(expf(-fabsf(x)));
}

// ---------------- K1: per-row softplus + inclusive prefix scan ----------------
__global__ void k_rowprefix(const float* __restrict__ raw) {
    __shared__ float ws[8];
    int i = blockIdx.x, j = threadIdx.x;
    int off = i * (i + 1) / 2;
    float v = 0.f;
    if (j <= i) v = softplusf(raw[off + j]);
    int lane = j & 31, w = j >> 5;
#pragma unroll
    for (int o = 1; o < 32; o <<= 1) { float u = __shfl_up_sync(0xffffffffu, v, o); if (lane >= o) v += u; }
    if (lane == 31) ws[w] = v;
    __syncthreads();
    if (w == 0) {
        float x = (lane < 8) ? ws[lane] : 0.f;
#pragma unroll
        for (int o = 1; o < 8; o <<= 1) { float u = __shfl_up_sync(0xffffffffu, x, o); if (lane >= o) x += u; }
        if (lane < 8) ws[lane] = x;
    }
    __syncthreads();
    if (w > 0) v += ws[w - 1];
    if (j <= i) {
        g_P[off + j] = v;
        if (j == i) g_rowsum[i] = v;
    }
}

// ---------------- K2: column prefix table (double) ----------------
__global__ void k_colpre() {
    __shared__ double ws[8];
    int jc = blockIdx.x, k = threadIdx.x;
    double v = 0.0;
    if (k >= jc) v = (double)g_P[k * (k + 1) / 2 + jc];
    int lane = k & 31, w = k >> 5;
#pragma unroll
    for (int o = 1; o < 32; o <<= 1) { double u = __shfl_up_sync(0xffffffffu, v, o); if (lane >= o) v += u; }
    if (lane == 31) ws[w] = v;
    __syncthreads();
    if (w == 0) {
        double x = (lane < 8) ? ws[lane] : 0.0;
#pragma unroll
        for (int o = 1; o < 8; o <<= 1) { double u = __shfl_up_sync(0xffffffffu, x, o); if (lane >= o) x += u; }
        if (lane < 8) ws[lane] = x;
    }
    __syncthreads();
    if (w > 0) v += ws[w - 1];
    g_colpre[jc * NMESH + k] = v;   // valid where k >= jc; others never read
}

// ---------------- K3: single-block metadata kernel ----------------
// step classification, lastup scan, sparse tables, PGE links, A prefix.
__global__ void k_meta(const float* __restrict__ h,
                       const float* __restrict__ m2,
                       const float* __restrict__ m3) {
    __shared__ float  lin[NMESH];
    __shared__ int    bufA[SLEN];
    __shared__ int    bufB[SLEN];
    __shared__ int    sc[1024];
    __shared__ double dsc[32];
    int tid = threadIdx.x;

    // lin = linspace(-1,1,N) -> row 0 of xx (xx[0][1] != xx[0][0]; yy[0][1]==yy[0][0])
    if (tid < NMESH) {
        const float* xx = (m2[1] != m2[0]) ? m2 : m3;
        lin[tid] = xx[tid];
    }
    __syncthreads();

    // per-step meta: exact float compares against the real mesh values
    for (int s = tid; s < SLEN; s += 1024) {
        float hc, hp;
        if (s == 0) { hc = 1.0f; hp = h[MSTEPS - 1]; }       // pseudo wrap step
        else { hc = h[s - 1]; hp = (s == 1) ? 1.0f : h[s - 2]; }
        int iu = 0, dd = INT_MAX;
        if (hc > hp) {             // sweep up: rows with alpha < hc reset full
            int lo = 0, hi = NMESH;
            while (lo < hi) { int m = (lo + hi) >> 1; if (lin[m] < hc) lo = m + 1; else hi = m; }
            iu = lo;
        } else if (hc < hp) {      // sweep down: clamp c to max j with beta_j <= hc
            int lo = 0, hi = NMESH;
            while (lo < hi) { int m = (lo + hi) >> 1; if (lin[m] <= hc) lo = m + 1; else hi = m; }
            dd = lo - 1;
        }
        bufA[s] = iu; bufB[s] = dd;
        g_iu[s] = iu; g_d[s] = dd;
    }
    __syncthreads();

    // lastup: inclusive max-scan of (up ? s : -1)
    {
        int base = tid * 4;
        int w0 = (bufA[base]     > 0) ? base     : -1;
        int w1 = (bufA[base + 1] > 0) ? base + 1 : -1;
        int w2 = (bufA[base + 2] > 0) ? base + 2 : -1;
        int w3 = (bufA[base + 3] > 0) ? base + 3 : -1;
        int l0 = w0, l1 = max(l0, w1), l2 = max(l1, w2), l3 = max(l2, w3);
        sc[tid] = l3;
        __syncthreads();
        for (int o = 1; o < 1024; o <<= 1) {
            int v = sc[tid];
            if (tid >= o) v = max(v, sc[tid - o]);
            __syncthreads();
            sc[tid] = v;
            __syncthreads();
        }
        int pre = (tid > 0) ? sc[tid - 1] : -1;
        g_lastup[base]     = max(pre, l0);
        g_lastup[base + 1] = max(pre, l1);
        g_lastup[base + 2] = max(pre, l2);
        g_lastup[base + 3] = max(pre, l3);
        if (tid == 1023) {
            int w4 = (bufA[4096] > 0) ? 4096 : -1;
            g_lastup[4096] = max(sc[1023], w4);
        }
    }
    __syncthreads();

    // sparse table over d (min). level 0 in bufB; bufA becomes scratch.
    {
        int *cur = bufB, *nxt = bufA;
        for (int i = tid; i < SLEN; i += 1024) g_STd[i] = cur[i];
        __syncthreads();
        for (int k = 1; k < LOGS; k++) {
            int half = 1 << (k - 1);
            for (int i = tid; i < SLEN; i += 1024) {
                int a = cur[i];
                int b = (i + half < SLEN) ? cur[i + half] : INT_MAX;
                int m = min(a, b);
                nxt[i] = m;
                g_STd[k * SLEN + i] = m;
            }
            __syncthreads();
            int* t = cur; cur = nxt; nxt = t;
        }
    }
    __syncthreads();
    // sparse table over iu (max). reload iu from global.
    {
        for (int i = tid; i < SLEN; i += 1024) bufB[i] = g_iu[i];
        __syncthreads();
        int *cur = bufB, *nxt = bufA;
        for (int i = tid; i < SLEN; i += 1024) g_STu[i] = cur[i];
        __syncthreads();
        for (int k = 1; k < LOGS; k++) {
            int half = 1 << (k - 1);
            for (int i = tid; i < SLEN; i += 1024) {
                int a = cur[i];
                int b = (i + half < SLEN) ? cur[i + half] : -1;
                int m = max(a, b);
                nxt[i] = m;
                g_STu[k * SLEN + i] = m;
            }
            __syncthreads();
            int* t = cur; cur = nxt; nxt = t;
        }
    }
    __syncthreads();

    // PGE links: rightmost s' < s with iu[s'] > iu[s] (step 0 has iu=255, always qualifies)
    for (int s = tid; s < SLEN; s += 1024) {
        int iu = g_iu[s];
        int lnk = -1;
        if (iu > 0 && iu < NMESH - 1) {
            int L = 0, R = s - 1;
            while (L < R) {
                int mid = (L + R + 1) >> 1;
                int len = R - mid + 1;
                int k = 31 - __clz(len);
                int mx = max(g_STu[k * SLEN + mid], g_STu[k * SLEN + R - (1 << k) + 1]);
                if (mx > iu) L = mid; else R = mid - 1;
            }
            lnk = L;
        }
        g_link[s] = lnk;
    }
    __syncthreads();

    // A prefix of rowsums (double)
    {
        double v = (tid < NMESH) ? (double)g_rowsum[tid] : 0.0;
        int lane = tid & 31, w = tid >> 5;
#pragma unroll
        for (int o = 1; o < 32; o <<= 1) { double u = __shfl_up_sync(0xffffffffu, v, o); if (lane >= o) v += u; }
        if (lane == 31) dsc[w] = v;
        __syncthreads();
        if (w == 0) {
            double x = dsc[lane];
#pragma unroll
            for (int o = 1; o < 32; o <<= 1) { double u = __shfl_up_sync(0xffffffffu, x, o); if (lane >= o) x += u; }
            dsc[lane] = x;
        }
        __syncthreads();
        if (w > 0) v += dsc[w - 1];
        if (tid < NMESH) g_A[tid + 1] = v;
        if (tid == 0) g_A[0] = 0.0;
    }
}

// ---------------- K4: per-output backward dominant-maxima walk ----------------
__global__ void k_main(float* __restrict__ out) {
    int t = blockIdx.x * blockDim.x + threadIdx.x;
    if (t >= MSTEPS) return;
    int T = t + 1;                 // scan step producing states[t+1]
    int s = g_lastup[T];
    int Vmin = INT_MAX;
    int lo = 0, right = T;
    double acc = 0.0;
    while (true) {
        if (s < right) {           // min d over (s, right]
            int l = s + 1, r = right;
            int len = r - l + 1;
            int k = 31 - __clz(len);
            int m1 = g_STd[k * SLEN + l];
            int m2 = g_STd[k * SLEN + r - (1 << k) + 1];
            Vmin = min(Vmin, min(m1, m2));
        }
        int hi = g_iu[s];          // group rows [lo, hi) share clamp Vmin; c_i = min(i, Vmin)
        if (Vmin >= hi - 1) {
            acc += g_A[hi] - g_A[lo];
        } else if (Vmin >= 0) {
            int m = max(lo, Vmin + 1);
            acc += g_A[m] - g_A[lo];
            acc += g_colpre[Vmin * NMESH + (hi - 1)] - g_colpre[Vmin * NMESH + (m - 1)];
        }
        if (hi >= NMESH - 1) break;   // rows 0..254 covered; row 255 is always all -1
        lo = hi;
        right = s;
        s = g_link[s];
    }
    double S = g_A[NMESH];
    out[t] = (float)((2.0 * acc - S) / S);
}

// ---------------- launch ----------------
extern "C" void kernel_launch(void* const* d_in, const int* in_sizes, int n_in,
                              void* d_out, int out_size) {
    const float* h   = nullptr;
    const float* raw = nullptr;
    const float* m2  = nullptr;
    const float* m3  = nullptr;
    for (int i = 0; i < n_in; i++) {
        if (in_sizes[i] == MSTEPS && !h)            h   = (const float*)d_in[i];
        else if (in_sizes[i] == TRI && !raw)        raw = (const float*)d_in[i];
        else if (in_sizes[i] == NMESH * NMESH) {
            if (!m2) m2 = (const float*)d_in[i];
            else     m3 = (const float*)d_in[i];
        }
    }
    if (!m3) m3 = m2;

    k_rowprefix<<<NMESH, NMESH>>>(raw);
    k_colpre<<<NMESH, NMESH>>>();
    k_meta<<<1, 1024>>>(h, m2, m3);
    k_main<<<MSTEPS / 256, 256>>>((float*)d_out);
}

// round 2
// speedup vs baseline: 1.0447x; 1.0447x over previous
#include <cuda_runtime.h>
#include <math.h>
#include <limits.h>

#define NMESH  256
#define MSTEPS 4096
#define SLEN   (MSTEPS + 1)     // scan steps 0..M (step 0 = pseudo init sweep-up at hc=1.0)
#define SLEN2  4104             // padded stride (multiple of 8)
#define LOGS   13
#define TRI    (NMESH * (NMESH + 1) / 2)
#define SENT   ((short)32767)

// ---- packed metadata blob (int16 + trailing doubles), built by k_meta ----
#define OFF_STD     0
#define OFF_IU      (LOGS * SLEN2)            // 53352
#define OFF_LINK    (OFF_IU + SLEN2)          // 57456
#define OFF_LASTUP  (OFF_LINK + SLEN2)        // 61560
#define OFF_A       (OFF_LASTUP + SLEN2)      // 65664 (shorts) -> byte 131328, 16B aligned
#define PACK_SHORTS (OFF_A + 1032)            // 257 doubles = 1028 shorts, pad to 1032
#define PACK_BYTES  (PACK_SHORTS * 2)         // 133392, divisible by 16

__device__ short  g_pack[PACK_SHORTS];
__device__ float  g_P[TRI];                   // per-row inclusive prefix of softplus density
__device__ float  g_rowsum[NMESH];
__device__ double g_colpre[NMESH * NMESH];    // colpre[j*N+i] = sum_{k=j..i} P_k(j)

__device__ __forceinline__ float softplusf(float x) {
    return fmaxf(x, 0.f) + log1pf(expf(-fabsf(x)));
}

// ---------------- K1: per-row softplus + inclusive prefix scan ----------------
__global__ void k_rowprefix(const float* __restrict__ raw) {
    __shared__ float ws[8];
    int i = blockIdx.x, j = threadIdx.x;
    int off = i * (i + 1) / 2;
    float v = 0.f;
    if (j <= i) v = softplusf(raw[off + j]);
    int lane = j & 31, w = j >> 5;
#pragma unroll
    for (int o = 1; o < 32; o <<= 1) { float u = __shfl_up_sync(0xffffffffu, v, o); if (lane >= o) v += u; }
    if (lane == 31) ws[w] = v;
    __syncthreads();
    if (w == 0) {
        float x = (lane < 8) ? ws[lane] : 0.f;
#pragma unroll
        for (int o = 1; o < 8; o <<= 1) { float u = __shfl_up_sync(0xffffffffu, x, o); if (lane >= o) x += u; }
        if (lane < 8) ws[lane] = x;
    }
    __syncthreads();
    if (w > 0) v += ws[w - 1];
    if (j <= i) {
        g_P[off + j] = v;
        if (j == i) g_rowsum[i] = v;
    }
}

// ---------------- K2: column prefix table (double) ----------------
__global__ void k_colpre() {
    __shared__ double ws[8];
    int jc = blockIdx.x, k = threadIdx.x;
    double v = 0.0;
    if (k >= jc) v = (double)g_P[k * (k + 1) / 2 + jc];
    int lane = k & 31, w = k >> 5;
#pragma unroll
    for (int o = 1; o < 32; o <<= 1) { double u = __shfl_up_sync(0xffffffffu, v, o); if (lane >= o) v += u; }
    if (lane == 31) ws[w] = v;
    __syncthreads();
    if (w == 0) {
        double x = (lane < 8) ? ws[lane] : 0.0;
#pragma unroll
        for (int o = 1; o < 8; o <<= 1) { double u = __shfl_up_sync(0xffffffffu, x, o); if (lane >= o) x += u; }
        if (lane < 8) ws[lane] = x;
    }
    __syncthreads();
    if (w > 0) v += ws[w - 1];
    g_colpre[jc * NMESH + k] = v;   // valid where k >= jc; others never read
}

// ---------------- K3: single-block metadata kernel (all smem) ----------------
// dyn smem layout: dsc[32] dbl | sc[1024] int | lin[256] f32 |
//                  st_u[LOGS*SLEN2] s16 | s_iu | s_d | bufA | bufB (each SLEN2 s16)
#define SMEM_META (256 + 4096 + 1024 + 2 * (LOGS * SLEN2 + 4 * SLEN2))

__global__ void k_meta(const float* __restrict__ h,
                       const float* __restrict__ m2,
                       const float* __restrict__ m3) {
    extern __shared__ char sraw[];
    double* dsc = (double*)sraw;
    int*    sc  = (int*)(dsc + 32);
    float*  lin = (float*)(sc + 1024);
    short*  st_u = (short*)(lin + 256);
    short*  s_iu = st_u + LOGS * SLEN2;
    short*  s_d  = s_iu + SLEN2;
    short*  bufA = s_d + SLEN2;
    short*  bufB = bufA + SLEN2;
    int tid = threadIdx.x;

    // lin = linspace(-1,1,N) -> pick the mesh whose row 0 varies (xx)
    if (tid < NMESH) {
        const float* xx = (m2[1] != m2[0]) ? m2 : m3;
        lin[tid] = xx[tid];
    }
    __syncthreads();

    // per-step meta: exact float compares against the real mesh values
    for (int s = tid; s < SLEN; s += 1024) {
        float hc, hp;
        if (s == 0) { hc = 1.0f; hp = h[MSTEPS - 1]; }
        else { hc = h[s - 1]; hp = (s == 1) ? 1.0f : h[s - 2]; }
        short iu = 0, dd = SENT;
        if (hc > hp) {             // sweep up: rows with alpha < hc reset full
            int lo = 0, hi = NMESH;
            while (lo < hi) { int m = (lo + hi) >> 1; if (lin[m] < hc) lo = m + 1; else hi = m; }
            iu = (short)lo;
        } else if (hc < hp) {      // sweep down: clamp c to max j with beta_j <= hc
            int lo = 0, hi = NMESH;
            while (lo < hi) { int m = (lo + hi) >> 1; if (lin[m] <= hc) lo = m + 1; else hi = m; }
            dd = (short)(lo - 1);
        }
        s_iu[s] = iu; s_d[s] = dd;
        g_pack[OFF_IU + s] = iu;
    }
    __syncthreads();

    // lastup: inclusive max-scan of (up ? s : -1)
    {
        int base = tid * 4;
        int w0 = (s_iu[base]     > 0) ? base     : -1;
        int w1 = (s_iu[base + 1] > 0) ? base + 1 : -1;
        int w2 = (s_iu[base + 2] > 0) ? base + 2 : -1;
        int w3 = (s_iu[base + 3] > 0) ? base + 3 : -1;
        int l0 = w0, l1 = max(l0, w1), l2 = max(l1, w2), l3 = max(l2, w3);
        sc[tid] = l3;
        __syncthreads();
        for (int o = 1; o < 1024; o <<= 1) {
            int v = sc[tid];
            if (tid >= o) v = max(v, sc[tid - o]);
            __syncthreads();
            sc[tid] = v;
            __syncthreads();
        }
        int pre = (tid > 0) ? sc[tid - 1] : -1;
        g_pack[OFF_LASTUP + base]     = (short)max(pre, l0);
        g_pack[OFF_LASTUP + base + 1] = (short)max(pre, l1);
        g_pack[OFF_LASTUP + base + 2] = (short)max(pre, l2);
        g_pack[OFF_LASTUP + base + 3] = (short)max(pre, l3);
        if (tid == 1023) {
            int w4 = (s_iu[4096] > 0) ? 4096 : -1;
            g_pack[OFF_LASTUP + 4096] = (short)max(sc[1023], w4);
        }
    }
    __syncthreads();

    // sparse table over d (min): ping-pong in smem, stream levels to g_pack
    {
        short *cur = s_d, *nxt = bufA;
        for (int i = tid; i < SLEN; i += 1024) g_pack[OFF_STD + i] = cur[i];
        __syncthreads();
        for (int k = 1; k < LOGS; k++) {
            int half = 1 << (k - 1);
            for (int i = tid; i < SLEN; i += 1024) {
                short a = cur[i];
                short b = (i + half < SLEN) ? cur[i + half] : SENT;
                short m = a < b ? a : b;
                nxt[i] = m;
                g_pack[OFF_STD + k * SLEN2 + i] = m;
            }
            __syncthreads();
            short* t = cur; cur = nxt; nxt = (nxt == bufA) ? bufB : bufA;
            if (cur == s_d) cur = t;   // unreachable; keeps compiler calm
        }
    }
    __syncthreads();

    // sparse table over iu (max), all levels resident in smem st_u
    {
        for (int i = tid; i < SLEN; i += 1024) st_u[i] = s_iu[i];
        __syncthreads();
        for (int k = 1; k < LOGS; k++) {
            int half = 1 << (k - 1);
            const short* prv = st_u + (k - 1) * SLEN2;
            short* nxt = st_u + k * SLEN2;
            for (int i = tid; i < SLEN; i += 1024) {
                short a = prv[i];
                short b = (i + half < SLEN) ? prv[i + half] : (short)-1;
                nxt[i] = a > b ? a : b;
            }
            __syncthreads();
        }
    }

    // PGE links: rightmost s' < s with iu[s'] > iu[s] (all lookups in smem)
    for (int s = tid; s < SLEN; s += 1024) {
        int iu = s_iu[s];
        int lnk = -1;
        if (iu > 0 && iu < NMESH - 1) {
            int L = 0, R = s - 1;
            while (L < R) {
                int mid = (L + R + 1) >> 1;
                int len = R - mid + 1;
                int k = 31 - __clz(len);
                int mx = max((int)st_u[k * SLEN2 + mid], (int)st_u[k * SLEN2 + R - (1 << k) + 1]);
                if (mx > iu) L = mid; else R = mid - 1;
            }
            lnk = L;
        }
        g_pack[OFF_LINK + s] = (short)lnk;
    }

    // A prefix of rowsums (double) into blob tail
    {
        double v = (tid < NMESH) ? (double)g_rowsum[tid] : 0.0;
        int lane = tid & 31, w = tid >> 5;
#pragma unroll
        for (int o = 1; o < 32; o <<= 1) { double u = __shfl_up_sync(0xffffffffu, v, o); if (lane >= o) v += u; }
        if (lane == 31) dsc[w] = v;
        __syncthreads();
        if (w == 0) {
            double x = dsc[lane];
#pragma unroll
            for (int o = 1; o < 32; o <<= 1) { double u = __shfl_up_sync(0xffffffffu, x, o); if (lane >= o) x += u; }
            dsc[lane] = x;
        }
        __syncthreads();
        double* gA = (double*)(g_pack + OFF_A);
        if (w > 0) v += dsc[w - 1];
        if (tid < NMESH) gA[tid + 1] = v;
        if (tid == 0) gA[0] = 0.0;
    }
}

// ---------------- K4: chain walk, all metadata in shared memory ----------------
__global__ void k_main(float* __restrict__ out) {
    extern __shared__ char sraw[];
    // bulk-copy the packed blob into smem (128-bit loads)
    {
        const uint4* src = (const uint4*)g_pack;
        uint4* dst = (uint4*)sraw;
        for (int i = threadIdx.x; i < PACK_BYTES / 16; i += blockDim.x) dst[i] = src[i];
    }
    __syncthreads();
    const short* STd    = (const short*)sraw;
    const short* iuA    = STd + OFF_IU;
    const short* linkA  = STd + OFF_LINK;
    const short* lastup = STd + OFF_LASTUP;
    const double* A     = (const double*)(sraw + OFF_A * 2);

    int t = blockIdx.x * blockDim.x + threadIdx.x;
    if (t >= MSTEPS) return;
    int T = t + 1;
    int s = lastup[T];
    int Vmin = INT_MAX;
    int lo = 0, right = T;
    double acc = 0.0;
    while (true) {
        if (s < right) {           // min d over (s, right]
            int l = s + 1, r = right;
            int len = r - l + 1;
            int k = 31 - __clz(len);
            int m1 = STd[k * SLEN2 + l];
            int m2 = STd[k * SLEN2 + r - (1 << k) + 1];
            Vmin = min(Vmin, min(m1, m2));
        }
        int hi = iuA[s];           // group rows [lo, hi) share clamp Vmin; c_i = min(i, Vmin)
        if (Vmin >= hi - 1) {
            acc += A[hi] - A[lo];
        } else if (Vmin >= 0) {
            int m = max(lo, Vmin + 1);
            acc += A[m] - A[lo];
            acc += g_colpre[Vmin * NMESH + (hi - 1)] - g_colpre[Vmin * NMESH + (m - 1)];
        }
        if (hi >= NMESH - 1) break;   // row 255 is always all -1
        lo = hi;
        right = s;
        s = linkA[s];
    }
    double S = A[NMESH];
    out[t] = (float)((2.0 * acc - S) / S);
}

// ---------------- launch ----------------
extern "C" void kernel_launch(void* const* d_in, const int* in_sizes, int n_in,
                              void* d_out, int out_size) {
    const float* h   = nullptr;
    const float* raw = nullptr;
    const float* m2  = nullptr;
    const float* m3  = nullptr;
    for (int i = 0; i < n_in; i++) {
        if (in_sizes[i] == MSTEPS && !h)            h   = (const float*)d_in[i];
        else if (in_sizes[i] == TRI && !raw)        raw = (const float*)d_in[i];
        else if (in_sizes[i] == NMESH * NMESH) {
            if (!m2) m2 = (const float*)d_in[i];
            else     m3 = (const float*)d_in[i];
        }
    }
    if (!m3) m3 = m2;

    static bool attr_done = false;
    if (!attr_done) {
        cudaFuncSetAttribute(k_meta, cudaFuncAttributeMaxDynamicSharedMemorySize, SMEM_META);
        cudaFuncSetAttribute(k_main, cudaFuncAttributeMaxDynamicSharedMemorySize, PACK_BYTES);
        attr_done = true;
    }

    k_rowprefix<<<NMESH, NMESH>>>(raw);
    k_colpre<<<NMESH, NMESH>>>();
    k_meta<<<1, 1024, SMEM_META>>>(h, m2, m3);
    k_main<<<32, 128, PACK_BYTES>>>((float*)d_out);
}